// round 4
// baseline (speedup 1.0000x reference)
#include <cuda_runtime.h>
#include <cuda_bf16.h>
#include <cstddef>

// DeformAttnOnnx: single-level deformable attention
//   value:              (16, 2500, 8, 32) fp32   [d_in[0]]
//   value_spatial_shapes (1,2) int64 (== 50x50, compile-time)  [d_in[1], unused]
//   sampling_locations: (16, 2000, 8, 1, 4, 2) fp32  [d_in[2]]
//   attention_weights:  (16, 2000, 8, 1, 4)    fp32  [d_in[3]]
//   out:                (16, 2000, 256) fp32
//
// Strategy: one 8-lane group per (b,q,h). Lane i of the group owns float4
// d-slice [4i, 4i+4). Each bilinear corner fetch is then one perfectly
// coalesced 128B line (the full D=32 row of value for that k,h). Groups are
// packed h-fastest inside a warp so the final store is 512B contiguous.
// All math in fp32; zeros-padding handled by unsigned-compare predication.

namespace {
constexpr int BS = 16;
constexpr int KK = 2500;      // 50*50
constexpr int H  = 8;
constexpr int D  = 32;
constexpr int NQ = 2000;
constexpr int FH = 50;
constexpr int FW = 50;
constexpr int GROUPS = BS * NQ * H;          // 256000
constexpr int THREADS = 256;
constexpr int TOTAL_THREADS = GROUPS * 8;    // 8 lanes per group
constexpr int BLOCKS = TOTAL_THREADS / THREADS;  // 8000
}

__global__ __launch_bounds__(THREADS) void deform_attn_kernel(
    const float4* __restrict__ value,   // (b, k, h, d/4)
    const float4* __restrict__ loc,     // (b, q, h, 2)  [8 floats = 2 float4]
    const float4* __restrict__ aw,      // (b, q, h)     [4 floats = 1 float4]
    float4* __restrict__ out)           // (b, q, h*8 + sub)
{
    const int tid = blockIdx.x * THREADS + threadIdx.x;
    const int sub = tid & 7;            // which float4 slice of D
    const int g   = tid >> 3;           // group id = ((b*NQ + q)*H + ?) with h fastest
    const int h   = g & 7;
    const int bq  = g >> 3;             // b*NQ + q
    const int b   = bq / NQ;

    // per-(b,q,h) sampling params: 8 loc floats + 4 weights
    const int lbase = bq * H + h;
    const float4 l0 = loc[lbase * 2 + 0];   // p0.x p0.y p1.x p1.y
    const float4 l1 = loc[lbase * 2 + 1];   // p2.x p2.y p3.x p3.y
    const float4 a  = aw[lbase];

    const float lx[4] = {l0.x, l0.z, l1.x, l1.z};
    const float ly[4] = {l0.y, l0.w, l1.y, l1.w};
    const float av[4] = {a.x, a.y, a.z, a.w};

    // value base for this (b, h, sub); k stride = H*D/4 = 64 float4
    const float4* vbase = value + ((size_t)b * KK * H + h) * (D / 4) + sub;

    float4 acc = make_float4(0.f, 0.f, 0.f, 0.f);

#pragma unroll
    for (int p = 0; p < 4; ++p) {
        // unnormalize: x = (2*loc - 1 + 1) * W/2 - 0.5 = loc*W - 0.5
        const float x = lx[p] * (float)FW - 0.5f;
        const float y = ly[p] * (float)FH - 0.5f;
        const float xf = floorf(x);
        const float yf = floorf(y);
        const int ix = (int)xf;
        const int iy = (int)yf;
        const float wx1 = x - xf, wx0 = 1.0f - wx1;
        const float wy1 = y - yf, wy0 = 1.0f - wy1;
        const float aa = av[p];

        const bool vx0 = (unsigned)ix       < (unsigned)FW;
        const bool vx1 = (unsigned)(ix + 1) < (unsigned)FW;
        const bool vy0 = (unsigned)iy       < (unsigned)FH;
        const bool vy1 = (unsigned)(iy + 1) < (unsigned)FH;

        const int r0 = iy * FW;
        const int r1 = r0 + FW;

        if (vy0 && vx0) {
            const float4 v = __ldg(vbase + (size_t)(r0 + ix) * (H * D / 4));
            const float w = aa * wx0 * wy0;
            acc.x += w * v.x; acc.y += w * v.y; acc.z += w * v.z; acc.w += w * v.w;
        }
        if (vy0 && vx1) {
            const float4 v = __ldg(vbase + (size_t)(r0 + ix + 1) * (H * D / 4));
            const float w = aa * wx1 * wy0;
            acc.x += w * v.x; acc.y += w * v.y; acc.z += w * v.z; acc.w += w * v.w;
        }
        if (vy1 && vx0) {
            const float4 v = __ldg(vbase + (size_t)(r1 + ix) * (H * D / 4));
            const float w = aa * wx0 * wy1;
            acc.x += w * v.x; acc.y += w * v.y; acc.z += w * v.z; acc.w += w * v.w;
        }
        if (vy1 && vx1) {
            const float4 v = __ldg(vbase + (size_t)(r1 + ix + 1) * (H * D / 4));
            const float w = aa * wx1 * wy1;
            acc.x += w * v.x; acc.y += w * v.y; acc.z += w * v.z; acc.w += w * v.w;
        }
    }

    // out[(b*NQ+q)*256 + h*32 + sub*4]  -> float4 index bq*64 + h*8 + sub
    out[(size_t)bq * 64 + h * 8 + sub] = acc;
}

extern "C" void kernel_launch(void* const* d_in, const int* in_sizes, int n_in,
                              void* d_out, int out_size) {
    (void)in_sizes; (void)n_in; (void)out_size;
    const float4* value = (const float4*)d_in[0];
    // d_in[1] = value_spatial_shapes (int64, constant 50x50) — compile-time constants
    const float4* loc   = (const float4*)d_in[2];
    const float4* aw    = (const float4*)d_in[3];
    float4* out         = (float4*)d_out;

    deform_attn_kernel<<<BLOCKS, THREADS>>>(value, loc, aw, out);
}